// round 14
// baseline (speedup 1.0000x reference)
#include <cuda_runtime.h>
#include <cstdint>

#define NB 8
#define NC 256
#define NM 128
#define NPIX 16384
#define EPSV 1e-6f

// ---------------- scratch ----------------
__device__ float g_QK[(size_t)NB*256*NPIX];   // 0-127 Qn, 128-255 Kn
__device__ float g_Ksum[NB*NM];
__device__ float g_xsum[NB*NC];
__device__ float g_vsum[NB*NC];
__device__ float g_kxT[(size_t)NB*NC*NM];     // [b][xc][m]
__device__ float g_matT[(size_t)NB*NC*NM];    // [b][c][m]

__device__ __forceinline__ unsigned smem_u32(const void* p){
    unsigned a; asm("{ .reg .u64 t; cvta.to.shared.u64 t, %1; cvt.u32.u64 %0, t; }":"=r"(a):"l"(p)); return a;
}
__device__ __forceinline__ void mma_tf32(float* d, const unsigned* a, const unsigned* b){
    asm volatile("mma.sync.aligned.m16n8k8.row.col.f32.tf32.tf32.f32 "
        "{%0,%1,%2,%3}, {%4,%5,%6,%7}, {%8,%9}, {%0,%1,%2,%3};"
        : "+f"(d[0]), "+f"(d[1]), "+f"(d[2]), "+f"(d[3])
        : "r"(a[0]), "r"(a[1]), "r"(a[2]), "r"(a[3]), "r"(b[0]), "r"(b[1]));
}
__device__ __forceinline__ void cpa(unsigned d, const float* s){
    asm volatile("cp.async.cg.shared.global [%0], [%1], 16;"::"r"(d),"l"(s));
}
#define CPA_COMMIT() asm volatile("cp.async.commit_group;" ::: "memory")
#define CPA_WAIT1()  asm volatile("cp.async.wait_group 1;" ::: "memory")
#define CPA_WAIT0()  asm volatile("cp.async.wait_group 0;" ::: "memory")

// -------- fills --------
// full A (K=128): [row 0..127][k 0..127], row stride 132
template<int NT>
__device__ __forceinline__ void fillA132(unsigned dst, const float* src, size_t stride, int tid){
    #pragma unroll
    for (int s = 0; s < 4096/NT; s++){
        int idx = tid + NT*s;
        int row = idx >> 5, kq = idx & 31;
        cpa(dst + (unsigned)(row*132 + 4*kq)*4u, src + (size_t)row*stride + 4*kq);
    }
}
// [row 0..127][k 0..31], stride 36
template<int NT>
__device__ __forceinline__ void fillT36(unsigned dst, const float* src, size_t stride, int tid){
    #pragma unroll
    for (int s = 0; s < 1024/NT; s++){
        int idx = tid + NT*s;
        int row = idx >> 3, kq = idx & 7;
        cpa(dst + (unsigned)(row*36 + 4*kq)*4u, src + (size_t)row*stride + 4*kq);
    }
}
// [k 0..31][n 0..127], stride 136
template<int NT>
__device__ __forceinline__ void fillKN(unsigned dst, const float* src, size_t stride, int tid){
    #pragma unroll
    for (int s = 0; s < 1024/NT; s++){
        int idx = tid + NT*s;
        int k = idx >> 5, nq = idx & 31;
        cpa(dst + (unsigned)(k*136 + 4*nq)*4u, src + (size_t)k*stride + 4*nq);
    }
}

// -------- 64x64 warp tile, 4 warps (128 thr): 32 MMAs per warp per BK=32 ----
// AS: A row stride. BKN=0: B [n][k] stride36; BKN=1: B [k][n] stride136
template<int AS, int BKN>
__device__ __forceinline__ void mma_stage64(const float* As, const float* Bs,
        float acc[4][8][4], int wm, int wn, int lane){
    const int lq = lane & 3, lr = lane >> 2;
    #pragma unroll
    for (int kk = 0; kk < 4; kk++){
        const int k0 = kk*8 + lq;
        unsigned a[4][4], bf[8][2];
        #pragma unroll
        for (int i = 0; i < 4; i++){
            int mr = wm*64 + i*16 + lr;
            a[i][0] = __float_as_uint(As[mr*AS + k0]);
            a[i][1] = __float_as_uint(As[(mr+8)*AS + k0]);
            a[i][2] = __float_as_uint(As[mr*AS + k0 + 4]);
            a[i][3] = __float_as_uint(As[(mr+8)*AS + k0 + 4]);
        }
        #pragma unroll
        for (int j = 0; j < 8; j++){
            int nc = wn*64 + j*8 + lr;
            if (BKN == 0){
                bf[j][0] = __float_as_uint(Bs[nc*36 + k0]);
                bf[j][1] = __float_as_uint(Bs[nc*36 + k0 + 4]);
            } else {
                bf[j][0] = __float_as_uint(Bs[k0*136 + nc]);
                bf[j][1] = __float_as_uint(Bs[(k0+4)*136 + nc]);
            }
        }
        #pragma unroll
        for (int i = 0; i < 4; i++)
            #pragma unroll
            for (int j = 0; j < 8; j++)
                mma_tf32(acc[i][j], a[i], bf[j]);
    }
}

// -------- 32x64 tile (8 warps, 256 thr) — used by matfix only --------
template<int AS, int BKN>
__device__ __forceinline__ void mma_stage(const float* As, const float* Bs,
        float acc[2][8][4], int wm, int wn, int lane){
    const int lq = lane & 3, lr = lane >> 2;
    #pragma unroll
    for (int kk = 0; kk < 4; kk++){
        const int k0 = kk*8 + lq;
        unsigned a[2][4], bf[8][2];
        #pragma unroll
        for (int i = 0; i < 2; i++){
            int mr = wm*32 + i*16 + lr;
            a[i][0] = __float_as_uint(As[mr*AS + k0]);
            a[i][1] = __float_as_uint(As[(mr+8)*AS + k0]);
            a[i][2] = __float_as_uint(As[mr*AS + k0 + 4]);
            a[i][3] = __float_as_uint(As[(mr+8)*AS + k0 + 4]);
        }
        #pragma unroll
        for (int j = 0; j < 8; j++){
            int nc = wn*64 + j*8 + lr;
            if (BKN == 0){
                bf[j][0] = __float_as_uint(Bs[nc*36 + k0]);
                bf[j][1] = __float_as_uint(Bs[nc*36 + k0 + 4]);
            } else {
                bf[j][0] = __float_as_uint(Bs[k0*136 + nc]);
                bf[j][1] = __float_as_uint(Bs[(k0+4)*136 + nc]);
            }
        }
        #pragma unroll
        for (int i = 0; i < 2; i++)
            #pragma unroll
            for (int j = 0; j < 8; j++)
                mma_tf32(acc[i][j], a[i], bf[j]);
    }
}

__global__ void zero_kernel(){
    const int total = NB*NM + 2*NB*NC + 2*NB*NC*NM;
    for (int i = blockIdx.x*blockDim.x + threadIdx.x; i < total; i += gridDim.x*blockDim.x){
        if (i < NB*NM) g_Ksum[i] = 0.f;
        else if (i < NB*NM + NB*NC) g_xsum[i - NB*NM] = 0.f;
        else if (i < NB*NM + 2*NB*NC) g_vsum[i - NB*NM - NB*NC] = 0.f;
        else if (i < NB*NM + 2*NB*NC + NB*NC*NM) g_kxT[i - NB*NM - 2*NB*NC] = 0.f;
        else g_matT[i - NB*NM - 2*NB*NC - NB*NC*NM] = 0.f;
    }
}

// ========== GEMM1: Q,K projections; 3-stage single-sync pipeline ==========
// grid (2 mt, 128 nblk, 8 b), 128 thr; 8 k-windows
#define QSTG 8960               // A(4608)+B(4352)
#define QAUX (3*QSTG)           // xs 256 | sred 128
#define QSMEM ((QAUX + 384)*4)  // 109056 B
__global__ __launch_bounds__(128, 2) void gemm_qk(
    const float* __restrict__ x,
    const float* __restrict__ Wq, const float* __restrict__ bq,
    const float* __restrict__ Wk, const float* __restrict__ bk)
{
    extern __shared__ float smf[];
    const unsigned sb = smem_u32(smf);
    const int mt = blockIdx.x, nblk = blockIdx.y, b = blockIdx.z;
    const int tid = threadIdx.x, lane = tid & 31, wid = tid >> 5;
    const int wm = wid & 1, wn = wid >> 1;
    const int n0 = nblk * 128;

    const float* W     = mt ? Wk : Wq;
    const float* biasp = mt ? bk : bq;
    const float* xb = x + (size_t)b*NC*NPIX + n0;

    float* xs   = smf + QAUX;        // 256
    float* sred = xs + 256;          // 128
    if (mt == 0){ xs[tid] = 0.f; xs[tid + 128] = 0.f; }

    float acc[4][8][4] = {};
    fillT36<128>(sb, W, NC, tid);
    fillKN<128>(sb + 4608*4, xb, NPIX, tid);
    CPA_COMMIT();
    fillT36<128>(sb + QSTG*4, W + 32, NC, tid);
    fillKN<128>(sb + (QSTG + 4608)*4, xb + (size_t)32*NPIX, NPIX, tid);
    CPA_COMMIT();
    for (int it = 0; it < 8; ++it){
        const int cur = it % 3;
        if (it == 7) CPA_WAIT0(); else CPA_WAIT1();
        __syncthreads();
        if (it + 2 < 8){
            const int nx = (it+2) % 3, kt = (it+2)*32;
            fillT36<128>(sb + (nx*QSTG)*4,        W + kt, NC, tid);
            fillKN<128>(sb + (nx*QSTG + 4608)*4,  xb + (size_t)kt*NPIX, NPIX, tid);
            CPA_COMMIT();
        }
        if (mt == 0){   // xsum partial from resident x tile
            const float* Bc = smf + cur*QSTG + 4608;
            int k = tid >> 2, part = tid & 3;
            float s = 0.f;
            #pragma unroll
            for (int p = 0; p < 32; p++) s += Bc[k*136 + part*32 + p];
            s += __shfl_down_sync(0xffffffff, s, 2);
            s += __shfl_down_sync(0xffffffff, s, 1);
            if (part == 0) xs[it*32 + k] += s;
        }
        mma_stage64<36,1>(smf + cur*QSTG, smf + cur*QSTG + 4608, acc, wm, wn, lane);
    }
    __syncthreads();

    // ---- epilogue: bias -> Tile; norms; float4 store; Ksum/xsum ----
    float* Tile = smf;               // 128x129, reuses stage buffers
    const int lq = lane & 3, lr = lane >> 2;
    #pragma unroll
    for (int i = 0; i < 4; i++){
        int r = wm*64 + i*16 + lr;
        float bA = biasp[r], bB = biasp[r+8];
        #pragma unroll
        for (int j = 0; j < 8; j++){
            int c = wn*64 + j*8 + 2*lq;
            Tile[r*129 + c]       = acc[i][j][0] + bA;
            Tile[r*129 + c + 1]   = acc[i][j][1] + bA;
            Tile[(r+8)*129 + c]   = acc[i][j][2] + bB;
            Tile[(r+8)*129 + c+1] = acc[i][j][3] + bB;
        }
    }
    __syncthreads();
    {
        float s = 0.f;
        #pragma unroll 16
        for (int r = 0; r < 128; r++){ float v = Tile[r*129 + tid]; s = fmaf(v, v, s); }
        sred[tid] = rsqrtf(s);
    }
    __syncthreads();
    {
        const int col4 = (tid & 31) * 4, rgrp = tid >> 5;
        float s0 = sred[col4], s1 = sred[col4+1], s2 = sred[col4+2], s3 = sred[col4+3];
        float* outp = g_QK + ((size_t)b*256 + (size_t)mt*128)*NPIX + n0;
        #pragma unroll 8
        for (int rr = 0; rr < 32; rr++){
            int r = rgrp*32 + rr;
            const float* tr = &Tile[r*129 + col4];
            *reinterpret_cast<float4*>(&outp[(size_t)r*NPIX + col4]) =
                make_float4(tr[0]*s0, tr[1]*s1, tr[2]*s2, tr[3]*s3);
        }
    }
    if (mt == 1){
        float s = 0.f;
        #pragma unroll 16
        for (int c = 0; c < 128; c++) s = fmaf(Tile[tid*129 + c], sred[c], s);
        atomicAdd(&g_Ksum[b*NM + tid], s);
    }
    if (mt == 0){
        atomicAdd(&g_xsum[b*NC + tid], xs[tid]);
        atomicAdd(&g_xsum[b*NC + 128 + tid], xs[128 + tid]);
    }
}

// ========== GEMM2: kxT[xc][m] += x @ Kn^T; 3-stage single-sync; 1024 px/block ====
// grid (16 chunks, 2 ch, 8 b), 128 thr; 32 stages
#define KSTG 9216
#define KSMEM (3*KSTG*4)        // 110592 B
__global__ __launch_bounds__(128, 2) void gemm_km(const float* __restrict__ x){
    extern __shared__ float smf[];
    const unsigned sb = smem_u32(smf);
    const int chunk = blockIdx.x, ch = blockIdx.y, b = blockIdx.z;
    const int tid = threadIdx.x, lane = tid & 31, wid = tid >> 5;
    const int wm = wid & 1, wn = wid >> 1;
    const int n0 = chunk * 1024;

    const float* xa = x + ((size_t)b*NC + (size_t)ch*128)*NPIX + n0;
    const float* Kn = g_QK + ((size_t)b*256 + 128)*NPIX + n0;

    float acc[4][8][4] = {};
    fillT36<128>(sb,                  xa, NPIX, tid);
    fillT36<128>(sb + 4608*4,         Kn, NPIX, tid);
    CPA_COMMIT();
    fillT36<128>(sb + KSTG*4,          xa + 32, NPIX, tid);
    fillT36<128>(sb + (KSTG + 4608)*4, Kn + 32, NPIX, tid);
    CPA_COMMIT();
    for (int it = 0; it < 32; ++it){
        const int cur = it % 3;
        if (it == 31) CPA_WAIT0(); else CPA_WAIT1();
        __syncthreads();
        if (it + 2 < 32){
            const int nx = (it+2) % 3, kt = (it+2)*32;
            fillT36<128>(sb + (nx*KSTG)*4,        xa + kt, NPIX, tid);
            fillT36<128>(sb + (nx*KSTG + 4608)*4, Kn + kt, NPIX, tid);
            CPA_COMMIT();
        }
        mma_stage64<36,0>(smf + cur*KSTG, smf + cur*KSTG + 4608, acc, wm, wn, lane);
    }

    const int lq = lane & 3, lr = lane >> 2;
    #pragma unroll
    for (int i = 0; i < 4; i++){
        int r = wm*64 + i*16 + lr;
        float* m0 = g_kxT + ((size_t)b*NC + ch*128 + r)*NM;
        float* m1 = m0 + 8*NM;
        #pragma unroll
        for (int j = 0; j < 8; j++){
            int c = wn*64 + j*8 + 2*lq;
            atomicAdd(&m0[c],   acc[i][j][0]);
            atomicAdd(&m0[c+1], acc[i][j][1]);
            atomicAdd(&m1[c],   acc[i][j][2]);
            atomicAdd(&m1[c+1], acc[i][j][3]);
        }
    }
}

// ========== matfix: matT += Wv@kxT^T (+ bv x Ksum on kk0); vsum partials ======
// grid (2 ch, 2 kk, 8 b), 256 thr; 4 stages each
#define MSTG 8960
#define MAUX (2*MSTG)
#define MSMEM ((MAUX + 640)*4)
__global__ __launch_bounds__(256, 2) void matfix(
    const float* __restrict__ Wv, const float* __restrict__ bv)
{
    extern __shared__ float smf[];
    const unsigned sb = smem_u32(smf);
    const int ch = blockIdx.x, kk = blockIdx.y, b = blockIdx.z;
    const int tid = threadIdx.x, lane = tid & 31, wid = tid >> 5;
    const int wm = wid & 3, wn = wid >> 2;

    float* xs   = smf + MAUX;        // 256
    float* ksm  = xs + 256;          // 128
    float* dsum = ksm + 128;         // 256
    xs[tid] = g_xsum[b*NC + tid];
    if (tid < 128) ksm[tid] = g_Ksum[b*NM + tid];
    __syncthreads();

    const float* WA = Wv + (size_t)ch*128*NC + kk*128;
    const float* KB = g_kxT + (size_t)b*NC*NM + (size_t)(kk*128)*NM;

    const int dn = tid & 127, dh = tid >> 7;
    float vsp = 0.f;
    float acc[2][8][4] = {};

    fillT36<256>(sb, WA, NC, tid);
    fillKN<256>(sb + 4608*4, KB, NM, tid);
    CPA_COMMIT();
    for (int it = 0; it < 4; ++it){
        const int cur = it & 1;
        if (it + 1 < 4){
            const int nx = (it+1) & 1, kt = (it+1)*32;
            fillT36<256>(sb + (nx*MSTG)*4,       WA + kt, NC, tid);
            fillKN<256>(sb + (nx*MSTG + 4608)*4, KB + (size_t)kt*NM, NM, tid);
            CPA_COMMIT(); CPA_WAIT1();
        } else CPA_WAIT0();
        __syncthreads();
        {
            const float* Ac = smf + cur*MSTG;
            const int kt = kk*128 + it*32;
            #pragma unroll
            for (int p = 0; p < 16; p++){
                int k = dh*16 + p;
                vsp = fmaf(Ac[dn*36 + k], xs[kt + k], vsp);
            }
        }
        mma_stage<36,1>(smf + cur*MSTG, smf + cur*MSTG + 4608, acc, wm, wn, lane);
        __syncthreads();
    }

    dsum[dh*128 + dn] = vsp;
    __syncthreads();
    if (tid < 128){
        float add = dsum[tid] + dsum[128 + tid];
        if (kk == 0) add += (float)NPIX * bv[ch*128 + tid];
        atomicAdd(&g_vsum[b*NC + ch*128 + tid], add);
    }

    const int lq = lane & 3, lr = lane >> 2;
    #pragma unroll
    for (int i = 0; i < 2; i++){
        int r = wm*32 + i*16 + lr;
        float bv0 = (kk == 0) ? bv[ch*128 + r]     : 0.f;
        float bv1 = (kk == 0) ? bv[ch*128 + r + 8] : 0.f;
        float* m0 = g_matT + ((size_t)b*NC + ch*128 + r)*NM;
        float* m1 = m0 + 8*NM;
        #pragma unroll
        for (int j = 0; j < 8; j++){
            int c = wn*64 + j*8 + 2*lq;
            atomicAdd(&m0[c],   acc[i][j][0] + bv0*ksm[c]);
            atomicAdd(&m0[c+1], acc[i][j][1] + bv0*ksm[c+1]);
            atomicAdd(&m1[c],   acc[i][j][2] + bv1*ksm[c]);
            atomicAdd(&m1[c+1], acc[i][j][3] + bv1*ksm[c+1]);
        }
    }
}

// ========== GEMM3: out[c][n]; resident matT; 4 n-tiles; 128 thr ==========
// grid (32 nquad, 2 ch, 8 b)
#define GB   16896
#define GAUX (GB + 2*4352)       // ks128|svs128|stl128
#define OSMEM ((GAUX + 512)*4)   // 104448 B
__global__ __launch_bounds__(128, 2) void gemm_out(
    const float* __restrict__ gamma, float* __restrict__ out)
{
    extern __shared__ float smf[];
    const unsigned sb = smem_u32(smf);
    const int nquad = blockIdx.x, ch = blockIdx.y, b = blockIdx.z;
    const int tid = threadIdx.x, lane = tid & 31, wid = tid >> 5;
    const int wm = wid & 1, wn = wid >> 1;

    float* ks   = smf + GAUX;
    float* svs  = ks + 128;
    float* stl  = svs + 128;
    ks[tid]  = g_Ksum[b*NM + tid] + EPSV;
    svs[tid] = g_vsum[b*NC + ch*128 + tid];

    const float* mA = g_matT + ((size_t)b*NC + ch*128)*NM;
    fillA132<128>(sb, mA, NM, tid);

    const int lq = lane & 3, lr = lane >> 2;

    for (int sub = 0; sub < 4; sub++){
        const int n0 = (nquad*4 + sub) * 128;
        const float* Qb = g_QK + (size_t)b*256*NPIX + n0;

        float acc[4][8][4] = {};
        float ddv = 0.f;

        fillKN<128>(sb + GB*4, Qb, NPIX, tid);
        CPA_COMMIT();
        for (int it = 0; it < 4; ++it){
            const int cur = it & 1;
            if (it + 1 < 4){
                fillKN<128>(sb + (GB + ((it+1)&1)*4352)*4,
                            Qb + (size_t)(it+1)*32*NPIX, NPIX, tid);
                CPA_COMMIT(); CPA_WAIT1();
            } else CPA_WAIT0();
            __syncthreads();
            {   // fused tailor dot: thread tid owns pixel tid
                const float* Bc = smf + GB + cur*4352;
                const int m0 = it*32;
                #pragma unroll
                for (int k = 0; k < 32; k++)
                    ddv = fmaf(Bc[k*136 + tid], ks[m0 + k], ddv);
            }
            mma_stage64<132,1>(smf + it*32, smf + GB + cur*4352, acc, wm, wn, lane);
            __syncthreads();
        }

        stl[tid] = gamma[0] / ((float)NPIX + ddv);
        __syncthreads();

        float* ob = out + ((size_t)b*NC + (size_t)ch*128)*NPIX + n0;
        #pragma unroll
        for (int i = 0; i < 4; i++){
            int r = wm*64 + i*16 + lr;
            float v0 = svs[r], v1 = svs[r+8];
            #pragma unroll
            for (int j = 0; j < 8; j++){
                int c = wn*64 + j*8 + 2*lq;
                float t0 = stl[c], t1 = stl[c+1];
                *reinterpret_cast<float2*>(&ob[(size_t)r*NPIX + c]) =
                    make_float2(t0*(v0 + acc[i][j][0]), t1*(v0 + acc[i][j][1]));
                *reinterpret_cast<float2*>(&ob[(size_t)(r+8)*NPIX + c]) =
                    make_float2(t0*(v1 + acc[i][j][2]), t1*(v1 + acc[i][j][3]));
            }
        }
        __syncthreads();
    }
}

// ---------------- launch ----------------
extern "C" void kernel_launch(void* const* d_in, const int* in_sizes, int n_in,
                              void* d_out, int out_size)
{
    const float* x     = (const float*)d_in[0];
    const float* Wq    = (const float*)d_in[1];
    const float* bq    = (const float*)d_in[2];
    const float* Wk    = (const float*)d_in[3];
    const float* bk    = (const float*)d_in[4];
    const float* Wv    = (const float*)d_in[5];
    const float* bv    = (const float*)d_in[6];
    const float* gamma = (const float*)d_in[7];
    float* out = (float*)d_out;

    static bool attr_done = false;
    if (!attr_done){
        cudaFuncSetAttribute(gemm_qk,  cudaFuncAttributeMaxDynamicSharedMemorySize, QSMEM);
        cudaFuncSetAttribute(gemm_km,  cudaFuncAttributeMaxDynamicSharedMemorySize, KSMEM);
        cudaFuncSetAttribute(matfix,   cudaFuncAttributeMaxDynamicSharedMemorySize, MSMEM);
        cudaFuncSetAttribute(gemm_out, cudaFuncAttributeMaxDynamicSharedMemorySize, OSMEM);
        attr_done = true;
    }

    zero_kernel<<<256, 256>>>();
    gemm_qk<<<dim3(2, 128, NB), 128, QSMEM>>>(x, Wq, bq, Wk, bk);
    gemm_km<<<dim3(16, 2, NB), 128, KSMEM>>>(x);
    matfix<<<dim3(2, 2, NB), 256, MSMEM>>>(Wv, bv);
    gemm_out<<<dim3(32, 2, NB), 128, OSMEM>>>(gamma, out);
}

// round 15
// speedup vs baseline: 1.0078x; 1.0078x over previous
#include <cuda_runtime.h>
#include <cstdint>

#define NB 8
#define NC 256
#define NM 128
#define NPIX 16384
#define EPSV 1e-6f

// ---------------- scratch ----------------
__device__ float g_QK[(size_t)NB*256*NPIX];   // 0-127 Qn, 128-255 Kn
__device__ float g_Ksum[NB*NM];
__device__ float g_xsum[NB*NC];
__device__ float g_vsum[NB*NC];
__device__ float g_kxT[(size_t)NB*NC*NM];     // [b][xc][m]
__device__ float g_matT[(size_t)NB*NC*NM];    // [b][c][m]

__device__ __forceinline__ unsigned smem_u32(const void* p){
    unsigned a; asm("{ .reg .u64 t; cvta.to.shared.u64 t, %1; cvt.u32.u64 %0, t; }":"=r"(a):"l"(p)); return a;
}
__device__ __forceinline__ void mma_tf32(float* d, const unsigned* a, const unsigned* b){
    asm volatile("mma.sync.aligned.m16n8k8.row.col.f32.tf32.tf32.f32 "
        "{%0,%1,%2,%3}, {%4,%5,%6,%7}, {%8,%9}, {%0,%1,%2,%3};"
        : "+f"(d[0]), "+f"(d[1]), "+f"(d[2]), "+f"(d[3])
        : "r"(a[0]), "r"(a[1]), "r"(a[2]), "r"(a[3]), "r"(b[0]), "r"(b[1]));
}
__device__ __forceinline__ void cpa(unsigned d, const float* s){
    asm volatile("cp.async.cg.shared.global [%0], [%1], 16;"::"r"(d),"l"(s));
}
#define CPA_COMMIT() asm volatile("cp.async.commit_group;" ::: "memory")
#define CPA_WAIT1()  asm volatile("cp.async.wait_group 1;" ::: "memory")
#define CPA_WAIT0()  asm volatile("cp.async.wait_group 0;" ::: "memory")

// -------- fills --------
// full A (K=128): [row 0..127][k 0..127], row stride 132
template<int NT>
__device__ __forceinline__ void fillA132(unsigned dst, const float* src, size_t stride, int tid){
    #pragma unroll
    for (int s = 0; s < 4096/NT; s++){
        int idx = tid + NT*s;
        int row = idx >> 5, kq = idx & 31;
        cpa(dst + (unsigned)(row*132 + 4*kq)*4u, src + (size_t)row*stride + 4*kq);
    }
}
// [row 0..127][k 0..31], stride 36
template<int NT>
__device__ __forceinline__ void fillT36(unsigned dst, const float* src, size_t stride, int tid){
    #pragma unroll
    for (int s = 0; s < 1024/NT; s++){
        int idx = tid + NT*s;
        int row = idx >> 3, kq = idx & 7;
        cpa(dst + (unsigned)(row*36 + 4*kq)*4u, src + (size_t)row*stride + 4*kq);
    }
}
// [k 0..31][n 0..127], stride 136
template<int NT>
__device__ __forceinline__ void fillKN(unsigned dst, const float* src, size_t stride, int tid){
    #pragma unroll
    for (int s = 0; s < 1024/NT; s++){
        int idx = tid + NT*s;
        int k = idx >> 5, nq = idx & 31;
        cpa(dst + (unsigned)(k*136 + 4*nq)*4u, src + (size_t)k*stride + 4*nq);
    }
}

// -------- 64x64 warp tile, 4 warps (128 thr): 32 MMAs per warp per BK=32 ----
// AS: A row stride. BKN=0: B [n][k] stride36; BKN=1: B [k][n] stride136
template<int AS, int BKN>
__device__ __forceinline__ void mma_stage64(const float* As, const float* Bs,
        float acc[4][8][4], int wm, int wn, int lane){
    const int lq = lane & 3, lr = lane >> 2;
    #pragma unroll
    for (int kk = 0; kk < 4; kk++){
        const int k0 = kk*8 + lq;
        unsigned a[4][4], bf[8][2];
        #pragma unroll
        for (int i = 0; i < 4; i++){
            int mr = wm*64 + i*16 + lr;
            a[i][0] = __float_as_uint(As[mr*AS + k0]);
            a[i][1] = __float_as_uint(As[(mr+8)*AS + k0]);
            a[i][2] = __float_as_uint(As[mr*AS + k0 + 4]);
            a[i][3] = __float_as_uint(As[(mr+8)*AS + k0 + 4]);
        }
        #pragma unroll
        for (int j = 0; j < 8; j++){
            int nc = wn*64 + j*8 + lr;
            if (BKN == 0){
                bf[j][0] = __float_as_uint(Bs[nc*36 + k0]);
                bf[j][1] = __float_as_uint(Bs[nc*36 + k0 + 4]);
            } else {
                bf[j][0] = __float_as_uint(Bs[k0*136 + nc]);
                bf[j][1] = __float_as_uint(Bs[(k0+4)*136 + nc]);
            }
        }
        #pragma unroll
        for (int i = 0; i < 4; i++)
            #pragma unroll
            for (int j = 0; j < 8; j++)
                mma_tf32(acc[i][j], a[i], bf[j]);
    }
}

// -------- 32x64 tile (8 warps, 256 thr) — used by matfix only --------
template<int AS, int BKN>
__device__ __forceinline__ void mma_stage(const float* As, const float* Bs,
        float acc[2][8][4], int wm, int wn, int lane){
    const int lq = lane & 3, lr = lane >> 2;
    #pragma unroll
    for (int kk = 0; kk < 4; kk++){
        const int k0 = kk*8 + lq;
        unsigned a[2][4], bf[8][2];
        #pragma unroll
        for (int i = 0; i < 2; i++){
            int mr = wm*32 + i*16 + lr;
            a[i][0] = __float_as_uint(As[mr*AS + k0]);
            a[i][1] = __float_as_uint(As[(mr+8)*AS + k0]);
            a[i][2] = __float_as_uint(As[mr*AS + k0 + 4]);
            a[i][3] = __float_as_uint(As[(mr+8)*AS + k0 + 4]);
        }
        #pragma unroll
        for (int j = 0; j < 8; j++){
            int nc = wn*64 + j*8 + lr;
            if (BKN == 0){
                bf[j][0] = __float_as_uint(Bs[nc*36 + k0]);
                bf[j][1] = __float_as_uint(Bs[nc*36 + k0 + 4]);
            } else {
                bf[j][0] = __float_as_uint(Bs[k0*136 + nc]);
                bf[j][1] = __float_as_uint(Bs[(k0+4)*136 + nc]);
            }
        }
        #pragma unroll
        for (int i = 0; i < 2; i++)
            #pragma unroll
            for (int j = 0; j < 8; j++)
                mma_tf32(acc[i][j], a[i], bf[j]);
    }
}

// tiny: zero the atomic accumulators only (must precede gemm_qk)
__global__ void zero_small(){
    const int total = NB*NM + 2*NB*NC;   // 5120
    for (int i = threadIdx.x; i < total; i += blockDim.x){
        if (i < NB*NM) g_Ksum[i] = 0.f;
        else if (i < NB*NM + NB*NC) g_xsum[i - NB*NM] = 0.f;
        else g_vsum[i - NB*NM - NB*NC] = 0.f;
    }
}

// ========== GEMM1: Q,K projections; 128 thr, 64x64 warp tiles ==========
// grid (2 mt, 128 nblk, 8 b); 8 stages of K=32
// Also zeroes g_kxT/g_matT via grid-stride (consumed only by later kernels).
#define QSTG 8960               // A(4608)+B(4352)
#define QAUX (2*QSTG)           // xs 256 | sred 128
#define QSMEM ((QAUX + 384)*4)  // 73216 B
__global__ __launch_bounds__(128, 2) void gemm_qk(
    const float* __restrict__ x,
    const float* __restrict__ Wq, const float* __restrict__ bq,
    const float* __restrict__ Wk, const float* __restrict__ bk)
{
    extern __shared__ float smf[];
    const unsigned sb = smem_u32(smf);
    const int mt = blockIdx.x, nblk = blockIdx.y, b = blockIdx.z;
    const int tid = threadIdx.x, lane = tid & 31, wid = tid >> 5;
    const int wm = wid & 1, wn = wid >> 1;
    const int n0 = nblk * 128;

    const float* W     = mt ? Wk : Wq;
    const float* biasp = mt ? bk : bq;
    const float* xb = x + (size_t)b*NC*NPIX + n0;

    float* xs   = smf + QAUX;        // 256
    float* sred = xs + 256;          // 128
    if (mt == 0){ xs[tid] = 0.f; xs[tid + 128] = 0.f; }

    float acc[4][8][4] = {};
    fillT36<128>(sb, W, NC, tid);
    fillKN<128>(sb + 4608*4, xb, NPIX, tid);
    CPA_COMMIT();

    // fold the big zeroing in here (overlaps with the first fills)
    {
        const int gthreads = 2*128*NB*128;   // 262144
        const int gid = ((blockIdx.z*gridDim.y + blockIdx.y)*gridDim.x
                         + blockIdx.x)*128 + tid;
        const int total = NB*NC*NM;          // 262144
        if (gid < total){ g_kxT[gid] = 0.f; g_matT[gid] = 0.f; }
        (void)gthreads;
    }

    for (int it = 0; it < 8; ++it){
        const int cur = it & 1;
        if (it + 1 < 8){
            const int nx = (it+1) & 1, kt = (it+1)*32;
            fillT36<128>(sb + (nx*QSTG)*4,        W + kt, NC, tid);
            fillKN<128>(sb + (nx*QSTG + 4608)*4,  xb + (size_t)kt*NPIX, NPIX, tid);
            CPA_COMMIT(); CPA_WAIT1();
        } else CPA_WAIT0();
        __syncthreads();
        if (mt == 0){   // xsum partial from resident x tile
            const float* Bc = smf + cur*QSTG + 4608;
            int k = tid >> 2, part = tid & 3;
            float s = 0.f;
            #pragma unroll
            for (int p = 0; p < 32; p++) s += Bc[k*136 + part*32 + p];
            s += __shfl_down_sync(0xffffffff, s, 2);
            s += __shfl_down_sync(0xffffffff, s, 1);
            if (part == 0) xs[it*32 + k] += s;
        }
        mma_stage64<36,1>(smf + cur*QSTG, smf + cur*QSTG + 4608, acc, wm, wn, lane);
        __syncthreads();
    }

    // ---- epilogue: bias -> Tile; norms; float4 store; Ksum/xsum ----
    float* Tile = smf;               // 128x129, reuses stage buffers
    const int lq = lane & 3, lr = lane >> 2;
    #pragma unroll
    for (int i = 0; i < 4; i++){
        int r = wm*64 + i*16 + lr;
        float bA = biasp[r], bB = biasp[r+8];
        #pragma unroll
        for (int j = 0; j < 8; j++){
            int c = wn*64 + j*8 + 2*lq;
            Tile[r*129 + c]       = acc[i][j][0] + bA;
            Tile[r*129 + c + 1]   = acc[i][j][1] + bA;
            Tile[(r+8)*129 + c]   = acc[i][j][2] + bB;
            Tile[(r+8)*129 + c+1] = acc[i][j][3] + bB;
        }
    }
    __syncthreads();
    {
        float s = 0.f;
        #pragma unroll 16
        for (int r = 0; r < 128; r++){ float v = Tile[r*129 + tid]; s = fmaf(v, v, s); }
        sred[tid] = rsqrtf(s);
    }
    __syncthreads();
    {
        const int col4 = (tid & 31) * 4, rgrp = tid >> 5;
        float s0 = sred[col4], s1 = sred[col4+1], s2 = sred[col4+2], s3 = sred[col4+3];
        float* outp = g_QK + ((size_t)b*256 + (size_t)mt*128)*NPIX + n0;
        #pragma unroll 8
        for (int rr = 0; rr < 32; rr++){
            int r = rgrp*32 + rr;
            const float* tr = &Tile[r*129 + col4];
            *reinterpret_cast<float4*>(&outp[(size_t)r*NPIX + col4]) =
                make_float4(tr[0]*s0, tr[1]*s1, tr[2]*s2, tr[3]*s3);
        }
    }
    if (mt == 1){
        float s = 0.f;
        #pragma unroll 16
        for (int c = 0; c < 128; c++) s = fmaf(Tile[tid*129 + c], sred[c], s);
        atomicAdd(&g_Ksum[b*NM + tid], s);
    }
    if (mt == 0){
        atomicAdd(&g_xsum[b*NC + tid], xs[tid]);
        atomicAdd(&g_xsum[b*NC + 128 + tid], xs[128 + tid]);
    }
}

// ========== GEMM2: kxT[xc][m] += x @ Kn^T; 1024 px/block; 128 thr ==========
// grid (16 chunks, 2 ch, 8 b); 32 stages
#define KSTG 9216
#define KSMEM (2*KSTG*4)
__global__ __launch_bounds__(128, 2) void gemm_km(const float* __restrict__ x){
    extern __shared__ float smf[];
    const unsigned sb = smem_u32(smf);
    const int chunk = blockIdx.x, ch = blockIdx.y, b = blockIdx.z;
    const int tid = threadIdx.x, lane = tid & 31, wid = tid >> 5;
    const int wm = wid & 1, wn = wid >> 1;
    const int n0 = chunk * 1024;

    const float* xa = x + ((size_t)b*NC + (size_t)ch*128)*NPIX + n0;
    const float* Kn = g_QK + ((size_t)b*256 + 128)*NPIX + n0;

    float acc[4][8][4] = {};
    fillT36<128>(sb,          xa, NPIX, tid);
    fillT36<128>(sb + 4608*4, Kn, NPIX, tid);
    CPA_COMMIT();
    for (int it = 0; it < 32; ++it){
        const int cur = it & 1;
        if (it + 1 < 32){
            const int nx = (it+1) & 1, kt = (it+1)*32;
            fillT36<128>(sb + (nx*KSTG)*4,        xa + kt, NPIX, tid);
            fillT36<128>(sb + (nx*KSTG + 4608)*4, Kn + kt, NPIX, tid);
            CPA_COMMIT(); CPA_WAIT1();
        } else CPA_WAIT0();
        __syncthreads();
        mma_stage64<36,0>(smf + cur*KSTG, smf + cur*KSTG + 4608, acc, wm, wn, lane);
        __syncthreads();
    }

    const int lq = lane & 3, lr = lane >> 2;
    #pragma unroll
    for (int i = 0; i < 4; i++){
        int r = wm*64 + i*16 + lr;
        float* m0 = g_kxT + ((size_t)b*NC + ch*128 + r)*NM;
        float* m1 = m0 + 8*NM;
        #pragma unroll
        for (int j = 0; j < 8; j++){
            int c = wn*64 + j*8 + 2*lq;
            atomicAdd(&m0[c],   acc[i][j][0]);
            atomicAdd(&m0[c+1], acc[i][j][1]);
            atomicAdd(&m1[c],   acc[i][j][2]);
            atomicAdd(&m1[c+1], acc[i][j][3]);
        }
    }
}

// ========== matfix: matT += Wv@kxT^T (+ bv x Ksum on kk0); vsum partials ======
// grid (2 ch, 2 kk, 8 b), 256 thr; 4 stages each
#define MSTG 8960
#define MAUX (2*MSTG)
#define MSMEM ((MAUX + 640)*4)
__global__ __launch_bounds__(256, 2) void matfix(
    const float* __restrict__ Wv, const float* __restrict__ bv)
{
    extern __shared__ float smf[];
    const unsigned sb = smem_u32(smf);
    const int ch = blockIdx.x, kk = blockIdx.y, b = blockIdx.z;
    const int tid = threadIdx.x, lane = tid & 31, wid = tid >> 5;
    const int wm = wid & 3, wn = wid >> 2;

    float* xs   = smf + MAUX;        // 256
    float* ksm  = xs + 256;          // 128
    float* dsum = ksm + 128;         // 256
    xs[tid] = g_xsum[b*NC + tid];
    if (tid < 128) ksm[tid] = g_Ksum[b*NM + tid];
    __syncthreads();

    const float* WA = Wv + (size_t)ch*128*NC + kk*128;
    const float* KB = g_kxT + (size_t)b*NC*NM + (size_t)(kk*128)*NM;

    const int dn = tid & 127, dh = tid >> 7;
    float vsp = 0.f;
    float acc[2][8][4] = {};

    fillT36<256>(sb, WA, NC, tid);
    fillKN<256>(sb + 4608*4, KB, NM, tid);
    CPA_COMMIT();
    for (int it = 0; it < 4; ++it){
        const int cur = it & 1;
        if (it + 1 < 4){
            const int nx = (it+1) & 1, kt = (it+1)*32;
            fillT36<256>(sb + (nx*MSTG)*4,       WA + kt, NC, tid);
            fillKN<256>(sb + (nx*MSTG + 4608)*4, KB + (size_t)kt*NM, NM, tid);
            CPA_COMMIT(); CPA_WAIT1();
        } else CPA_WAIT0();
        __syncthreads();
        {
            const float* Ac = smf + cur*MSTG;
            const int kt = kk*128 + it*32;
            #pragma unroll
            for (int p = 0; p < 16; p++){
                int k = dh*16 + p;
                vsp = fmaf(Ac[dn*36 + k], xs[kt + k], vsp);
            }
        }
        mma_stage<36,1>(smf + cur*MSTG, smf + cur*MSTG + 4608, acc, wm, wn, lane);
        __syncthreads();
    }

    dsum[dh*128 + dn] = vsp;
    __syncthreads();
    if (tid < 128){
        float add = dsum[tid] + dsum[128 + tid];
        if (kk == 0) add += (float)NPIX * bv[ch*128 + tid];
        atomicAdd(&g_vsum[b*NC + ch*128 + tid], add);
    }

    const int lq = lane & 3, lr = lane >> 2;
    #pragma unroll
    for (int i = 0; i < 2; i++){
        int r = wm*32 + i*16 + lr;
        float bv0 = (kk == 0) ? bv[ch*128 + r]     : 0.f;
        float bv1 = (kk == 0) ? bv[ch*128 + r + 8] : 0.f;
        float* m0 = g_matT + ((size_t)b*NC + ch*128 + r)*NM;
        float* m1 = m0 + 8*NM;
        #pragma unroll
        for (int j = 0; j < 8; j++){
            int c = wn*64 + j*8 + 2*lq;
            atomicAdd(&m0[c],   acc[i][j][0] + bv0*ksm[c]);
            atomicAdd(&m0[c+1], acc[i][j][1] + bv0*ksm[c+1]);
            atomicAdd(&m1[c],   acc[i][j][2] + bv1*ksm[c]);
            atomicAdd(&m1[c+1], acc[i][j][3] + bv1*ksm[c+1]);
        }
    }
}

// ========== GEMM3: out[c][n]; resident matT; 4 n-tiles; 128 thr ==========
// grid (32 nquad, 2 ch, 8 b)
#define GB   16896
#define GAUX (GB + 2*4352)       // ks128|svs128|stl128
#define OSMEM ((GAUX + 512)*4)   // 104448 B
__global__ __launch_bounds__(128, 2) void gemm_out(
    const float* __restrict__ gamma, float* __restrict__ out)
{
    extern __shared__ float smf[];
    const unsigned sb = smem_u32(smf);
    const int nquad = blockIdx.x, ch = blockIdx.y, b = blockIdx.z;
    const int tid = threadIdx.x, lane = tid & 31, wid = tid >> 5;
    const int wm = wid & 1, wn = wid >> 1;

    float* ks   = smf + GAUX;
    float* svs  = ks + 128;
    float* stl  = svs + 128;
    ks[tid]  = g_Ksum[b*NM + tid] + EPSV;
    svs[tid] = g_vsum[b*NC + ch*128 + tid];

    const float* mA = g_matT + ((size_t)b*NC + ch*128)*NM;
    fillA132<128>(sb, mA, NM, tid);

    const int lq = lane & 3, lr = lane >> 2;

    for (int sub = 0; sub < 4; sub++){
        const int n0 = (nquad*4 + sub) * 128;
        const float* Qb = g_QK + (size_t)b*256*NPIX + n0;

        float acc[4][8][4] = {};
        float ddv = 0.f;

        fillKN<128>(sb + GB*4, Qb, NPIX, tid);
        CPA_COMMIT();
        for (int it = 0; it < 4; ++it){
            const int cur = it & 1;
            if (it + 1 < 4){
                fillKN<128>(sb + (GB + ((it+1)&1)*4352)*4,
                            Qb + (size_t)(it+1)*32*NPIX, NPIX, tid);
                CPA_COMMIT(); CPA_WAIT1();
            } else CPA_WAIT0();
            __syncthreads();
            {   // fused tailor dot: thread tid owns pixel tid
                const float* Bc = smf + GB + cur*4352;
                const int m0 = it*32;
                #pragma unroll
                for (int k = 0; k < 32; k++)
                    ddv = fmaf(Bc[k*136 + tid], ks[m0 + k], ddv);
            }
            mma_stage64<132,1>(smf + it*32, smf + GB + cur*4352, acc, wm, wn, lane);
            __syncthreads();
        }

        stl[tid] = gamma[0] / ((float)NPIX + ddv);
        __syncthreads();

        float* ob = out + ((size_t)b*NC + (size_t)ch*128)*NPIX + n0;
        #pragma unroll
        for (int i = 0; i < 4; i++){
            int r = wm*64 + i*16 + lr;
            float v0 = svs[r], v1 = svs[r+8];
            #pragma unroll
            for (int j = 0; j < 8; j++){
                int c = wn*64 + j*8 + 2*lq;
                float t0 = stl[c], t1 = stl[c+1];
                *reinterpret_cast<float2*>(&ob[(size_t)r*NPIX + c]) =
                    make_float2(t0*(v0 + acc[i][j][0]), t1*(v0 + acc[i][j][1]));
                *reinterpret_cast<float2*>(&ob[(size_t)(r+8)*NPIX + c]) =
                    make_float2(t0*(v1 + acc[i][j][2]), t1*(v1 + acc[i][j][3]));
            }
        }
        __syncthreads();
    }
}

// ---------------- launch ----------------
extern "C" void kernel_launch(void* const* d_in, const int* in_sizes, int n_in,
                              void* d_out, int out_size)
{
    const float* x     = (const float*)d_in[0];
    const float* Wq    = (const float*)d_in[1];
    const float* bq    = (const float*)d_in[2];
    const float* Wk    = (const float*)d_in[3];
    const float* bk    = (const float*)d_in[4];
    const float* Wv    = (const float*)d_in[5];
    const float* bv    = (const float*)d_in[6];
    const float* gamma = (const float*)d_in[7];
    float* out = (float*)d_out;

    static bool attr_done = false;
    if (!attr_done){
        cudaFuncSetAttribute(gemm_qk,  cudaFuncAttributeMaxDynamicSharedMemorySize, QSMEM);
        cudaFuncSetAttribute(gemm_km,  cudaFuncAttributeMaxDynamicSharedMemorySize, KSMEM);
        cudaFuncSetAttribute(matfix,   cudaFuncAttributeMaxDynamicSharedMemorySize, MSMEM);
        cudaFuncSetAttribute(gemm_out, cudaFuncAttributeMaxDynamicSharedMemorySize, OSMEM);
        attr_done = true;
    }

    zero_small<<<1, 256>>>();
    gemm_qk<<<dim3(2, 128, NB), 128, QSMEM>>>(x, Wq, bq, Wk, bk);
    gemm_km<<<dim3(16, 2, NB), 128, KSMEM>>>(x);
    matfix<<<dim3(2, 2, NB), 256, MSMEM>>>(Wv, bv);
    gemm_out<<<dim3(32, 2, NB), 128, OSMEM>>>(gamma, out);
}

// round 16
// speedup vs baseline: 1.0483x; 1.0402x over previous
#include <cuda_runtime.h>
#include <cstdint>

#define NB 8
#define NC 256
#define NM 128
#define NPIX 16384
#define EPSV 1e-6f
#define NBLK 37   // blocks per batch -> 37*8 = 296 = exactly one wave @ 2 CTA/SM

// ---------------- scratch ----------------
__device__ float g_QK[(size_t)NB*256*NPIX];   // 0-127 Qn, 128-255 Kn
__device__ float g_Ksum[NB*NM];
__device__ float g_xsum[NB*NC];
__device__ float g_vsum[NB*NC];
__device__ float g_kxT[(size_t)NB*NC*NM];     // [b][xc][m]
__device__ float g_matT[(size_t)NB*NC*NM];    // [b][c][m]

__device__ __forceinline__ unsigned smem_u32(const void* p){
    unsigned a; asm("{ .reg .u64 t; cvta.to.shared.u64 t, %1; cvt.u32.u64 %0, t; }":"=r"(a):"l"(p)); return a;
}
__device__ __forceinline__ void mma_tf32(float* d, const unsigned* a, const unsigned* b){
    asm volatile("mma.sync.aligned.m16n8k8.row.col.f32.tf32.tf32.f32 "
        "{%0,%1,%2,%3}, {%4,%5,%6,%7}, {%8,%9}, {%0,%1,%2,%3};"
        : "+f"(d[0]), "+f"(d[1]), "+f"(d[2]), "+f"(d[3])
        : "r"(a[0]), "r"(a[1]), "r"(a[2]), "r"(a[3]), "r"(b[0]), "r"(b[1]));
}
__device__ __forceinline__ void cpa(unsigned d, const float* s){
    asm volatile("cp.async.cg.shared.global [%0], [%1], 16;"::"r"(d),"l"(s));
}
#define CPA_COMMIT() asm volatile("cp.async.commit_group;" ::: "memory")
#define CPA_WAIT1()  asm volatile("cp.async.wait_group 1;" ::: "memory")
#define CPA_WAIT0()  asm volatile("cp.async.wait_group 0;" ::: "memory")

// -------- fills --------
template<int NT>
__device__ __forceinline__ void fillA132(unsigned dst, const float* src, size_t stride, int tid){
    #pragma unroll
    for (int s = 0; s < 4096/NT; s++){
        int idx = tid + NT*s;
        int row = idx >> 5, kq = idx & 31;
        cpa(dst + (unsigned)(row*132 + 4*kq)*4u, src + (size_t)row*stride + 4*kq);
    }
}
template<int NT>
__device__ __forceinline__ void fillT36(unsigned dst, const float* src, size_t stride, int tid){
    #pragma unroll
    for (int s = 0; s < 1024/NT; s++){
        int idx = tid + NT*s;
        int row = idx >> 3, kq = idx & 7;
        cpa(dst + (unsigned)(row*36 + 4*kq)*4u, src + (size_t)row*stride + 4*kq);
    }
}
template<int NT>
__device__ __forceinline__ void fillKN(unsigned dst, const float* src, size_t stride, int tid){
    #pragma unroll
    for (int s = 0; s < 1024/NT; s++){
        int idx = tid + NT*s;
        int k = idx >> 5, nq = idx & 31;
        cpa(dst + (unsigned)(k*136 + 4*nq)*4u, src + (size_t)k*stride + 4*nq);
    }
}

// -------- 64x64 warp tile, 4 warps: 32 MMAs per warp per BK=32 ----
template<int AS, int BKN>
__device__ __forceinline__ void mma_stage64(const float* As, const float* Bs,
        float acc[4][8][4], int wm, int wn, int lane){
    const int lq = lane & 3, lr = lane >> 2;
    #pragma unroll
    for (int kk = 0; kk < 4; kk++){
        const int k0 = kk*8 + lq;
        unsigned a[4][4], bf[8][2];
        #pragma unroll
        for (int i = 0; i < 4; i++){
            int mr = wm*64 + i*16 + lr;
            a[i][0] = __float_as_uint(As[mr*AS + k0]);
            a[i][1] = __float_as_uint(As[(mr+8)*AS + k0]);
            a[i][2] = __float_as_uint(As[mr*AS + k0 + 4]);
            a[i][3] = __float_as_uint(As[(mr+8)*AS + k0 + 4]);
        }
        #pragma unroll
        for (int j = 0; j < 8; j++){
            int nc = wn*64 + j*8 + lr;
            if (BKN == 0){
                bf[j][0] = __float_as_uint(Bs[nc*36 + k0]);
                bf[j][1] = __float_as_uint(Bs[nc*36 + k0 + 4]);
            } else {
                bf[j][0] = __float_as_uint(Bs[k0*136 + nc]);
                bf[j][1] = __float_as_uint(Bs[(k0+4)*136 + nc]);
            }
        }
        #pragma unroll
        for (int i = 0; i < 4; i++)
            #pragma unroll
            for (int j = 0; j < 8; j++)
                mma_tf32(acc[i][j], a[i], bf[j]);
    }
}

// -------- 32x64 tile (8 warps, 256 thr) — matfix only --------
template<int AS, int BKN>
__device__ __forceinline__ void mma_stage(const float* As, const float* Bs,
        float acc[2][8][4], int wm, int wn, int lane){
    const int lq = lane & 3, lr = lane >> 2;
    #pragma unroll
    for (int kk = 0; kk < 4; kk++){
        const int k0 = kk*8 + lq;
        unsigned a[2][4], bf[8][2];
        #pragma unroll
        for (int i = 0; i < 2; i++){
            int mr = wm*32 + i*16 + lr;
            a[i][0] = __float_as_uint(As[mr*AS + k0]);
            a[i][1] = __float_as_uint(As[(mr+8)*AS + k0]);
            a[i][2] = __float_as_uint(As[mr*AS + k0 + 4]);
            a[i][3] = __float_as_uint(As[(mr+8)*AS + k0 + 4]);
        }
        #pragma unroll
        for (int j = 0; j < 8; j++){
            int nc = wn*64 + j*8 + lr;
            if (BKN == 0){
                bf[j][0] = __float_as_uint(Bs[nc*36 + k0]);
                bf[j][1] = __float_as_uint(Bs[nc*36 + k0 + 4]);
            } else {
                bf[j][0] = __float_as_uint(Bs[k0*136 + nc]);
                bf[j][1] = __float_as_uint(Bs[(k0+4)*136 + nc]);
            }
        }
        #pragma unroll
        for (int i = 0; i < 2; i++)
            #pragma unroll
            for (int j = 0; j < 8; j++)
                mma_tf32(acc[i][j], a[i], bf[j]);
    }
}

// tiny: zero the atomic accumulators (must precede gemm_qk)
__global__ void zero_small(){
    const int total = NB*NM + 2*NB*NC;
    for (int i = threadIdx.x; i < total; i += blockDim.x){
        if (i < NB*NM) g_Ksum[i] = 0.f;
        else if (i < NB*NM + NB*NC) g_xsum[i - NB*NM] = 0.f;
        else g_vsum[i - NB*NM - NB*NC] = 0.f;
    }
}

// ========== GEMM1: Q,K projections (unchanged from best) ==========
#define QSTG 8960
#define QAUX (2*QSTG)
#define QSMEM ((QAUX + 384)*4)
__global__ __launch_bounds__(128, 2) void gemm_qk(
    const float* __restrict__ x,
    const float* __restrict__ Wq, const float* __restrict__ bq,
    const float* __restrict__ Wk, const float* __restrict__ bk)
{
    extern __shared__ float smf[];
    const unsigned sb = smem_u32(smf);
    const int mt = blockIdx.x, nblk = blockIdx.y, b = blockIdx.z;
    const int tid = threadIdx.x, lane = tid & 31, wid = tid >> 5;
    const int wm = wid & 1, wn = wid >> 1;
    const int n0 = nblk * 128;

    const float* W     = mt ? Wk : Wq;
    const float* biasp = mt ? bk : bq;
    const float* xb = x + (size_t)b*NC*NPIX + n0;

    float* xs   = smf + QAUX;
    float* sred = xs + 256;
    if (mt == 0){ xs[tid] = 0.f; xs[tid + 128] = 0.f; }

    float acc[4][8][4] = {};
    fillT36<128>(sb, W, NC, tid);
    fillKN<128>(sb + 4608*4, xb, NPIX, tid);
    CPA_COMMIT();

    // fold the big zeroing in (overlaps with first fills)
    {
        const int gid = ((blockIdx.z*gridDim.y + blockIdx.y)*gridDim.x
                         + blockIdx.x)*128 + tid;
        if (gid < NB*NC*NM){ g_kxT[gid] = 0.f; g_matT[gid] = 0.f; }
    }

    for (int it = 0; it < 8; ++it){
        const int cur = it & 1;
        if (it + 1 < 8){
            const int nx = (it+1) & 1, kt = (it+1)*32;
            fillT36<128>(sb + (nx*QSTG)*4,        W + kt, NC, tid);
            fillKN<128>(sb + (nx*QSTG + 4608)*4,  xb + (size_t)kt*NPIX, NPIX, tid);
            CPA_COMMIT(); CPA_WAIT1();
        } else CPA_WAIT0();
        __syncthreads();
        if (mt == 0){
            const float* Bc = smf + cur*QSTG + 4608;
            int k = tid >> 2, part = tid & 3;
            float s = 0.f;
            #pragma unroll
            for (int p = 0; p < 32; p++) s += Bc[k*136 + part*32 + p];
            s += __shfl_down_sync(0xffffffff, s, 2);
            s += __shfl_down_sync(0xffffffff, s, 1);
            if (part == 0) xs[it*32 + k] += s;
        }
        mma_stage64<36,1>(smf + cur*QSTG, smf + cur*QSTG + 4608, acc, wm, wn, lane);
        __syncthreads();
    }

    float* Tile = smf;
    const int lq = lane & 3, lr = lane >> 2;
    #pragma unroll
    for (int i = 0; i < 4; i++){
        int r = wm*64 + i*16 + lr;
        float bA = biasp[r], bB = biasp[r+8];
        #pragma unroll
        for (int j = 0; j < 8; j++){
            int c = wn*64 + j*8 + 2*lq;
            Tile[r*129 + c]       = acc[i][j][0] + bA;
            Tile[r*129 + c + 1]   = acc[i][j][1] + bA;
            Tile[(r+8)*129 + c]   = acc[i][j][2] + bB;
            Tile[(r+8)*129 + c+1] = acc[i][j][3] + bB;
        }
    }
    __syncthreads();
    {
        float s = 0.f;
        #pragma unroll 16
        for (int r = 0; r < 128; r++){ float v = Tile[r*129 + tid]; s = fmaf(v, v, s); }
        sred[tid] = rsqrtf(s);
    }
    __syncthreads();
    {
        const int col4 = (tid & 31) * 4, rgrp = tid >> 5;
        float s0 = sred[col4], s1 = sred[col4+1], s2 = sred[col4+2], s3 = sred[col4+3];
        float* outp = g_QK + ((size_t)b*256 + (size_t)mt*128)*NPIX + n0;
        #pragma unroll 8
        for (int rr = 0; rr < 32; rr++){
            int r = rgrp*32 + rr;
            const float* tr = &Tile[r*129 + col4];
            *reinterpret_cast<float4*>(&outp[(size_t)r*NPIX + col4]) =
                make_float4(tr[0]*s0, tr[1]*s1, tr[2]*s2, tr[3]*s3);
        }
    }
    if (mt == 1){
        float s = 0.f;
        #pragma unroll 16
        for (int c = 0; c < 128; c++) s = fmaf(Tile[tid*129 + c], sred[c], s);
        atomicAdd(&g_Ksum[b*NM + tid], s);
    }
    if (mt == 0){
        atomicAdd(&g_xsum[b*NC + tid], xs[tid]);
        atomicAdd(&g_xsum[b*NC + 128 + tid], xs[128 + tid]);
    }
}

// ========== GEMM2: kxT += x @ Kn^T; single perfect wave (37 blocks/batch) ======
// per batch: 1024 units (2 ch x 512 stages of 32 px); block does ~28 units,
// flushing acc atomically at ch boundary / range end.
#define KSTG 9216
#define KSMEM (2*KSTG*4)
__global__ __launch_bounds__(128, 2) void gemm_km(const float* __restrict__ x){
    extern __shared__ float smf[];
    const unsigned sb = smem_u32(smf);
    const int bi = blockIdx.x, b = blockIdx.y;
    const int tid = threadIdx.x, lane = tid & 31, wid = tid >> 5;
    const int wm = wid & 1, wn = wid >> 1;
    const int u0 = (bi * 1024) / NBLK, u1 = ((bi + 1) * 1024) / NBLK;

    const float* xbase = x + (size_t)b*NC*NPIX;
    const float* Kbase = g_QK + ((size_t)b*256 + 128)*NPIX;

    float acc[4][8][4] = {};

    {   // prefetch unit u0
        int ch = u0 >> 9, st = u0 & 511;
        fillT36<128>(sb,          xbase + (size_t)ch*128*NPIX + st*32, NPIX, tid);
        fillT36<128>(sb + 4608*4, Kbase + st*32, NPIX, tid);
        CPA_COMMIT();
    }
    for (int u = u0; u < u1; ++u){
        const int cur = (u - u0) & 1;
        if (u + 1 < u1){
            const int nx = (u - u0 + 1) & 1;
            int ch = (u+1) >> 9, st = (u+1) & 511;
            fillT36<128>(sb + (nx*KSTG)*4,        xbase + (size_t)ch*128*NPIX + st*32, NPIX, tid);
            fillT36<128>(sb + (nx*KSTG + 4608)*4, Kbase + st*32, NPIX, tid);
            CPA_COMMIT(); CPA_WAIT1();
        } else CPA_WAIT0();
        __syncthreads();
        mma_stage64<36,0>(smf + cur*KSTG, smf + cur*KSTG + 4608, acc, wm, wn, lane);
        __syncthreads();

        const bool flush = (u + 1 == u1) || ((u >> 9) != ((u + 1) >> 9));
        if (flush){
            const int ch = u >> 9;
            const int lq = lane & 3, lr = lane >> 2;
            #pragma unroll
            for (int i = 0; i < 4; i++){
                int r = wm*64 + i*16 + lr;
                float* m0 = g_kxT + ((size_t)b*NC + ch*128 + r)*NM;
                float* m1 = m0 + 8*NM;
                #pragma unroll
                for (int j = 0; j < 8; j++){
                    int c = wn*64 + j*8 + 2*lq;
                    atomicAdd(&m0[c],   acc[i][j][0]);
                    atomicAdd(&m0[c+1], acc[i][j][1]);
                    atomicAdd(&m1[c],   acc[i][j][2]);
                    atomicAdd(&m1[c+1], acc[i][j][3]);
                }
            }
            #pragma unroll
            for (int i = 0; i < 4; i++)
                #pragma unroll
                for (int j = 0; j < 8; j++)
                    #pragma unroll
                    for (int q = 0; q < 4; q++) acc[i][j][q] = 0.f;
        }
    }
}

// ========== matfix (unchanged) ==========
#define MSTG 8960
#define MAUX (2*MSTG)
#define MSMEM ((MAUX + 640)*4)
__global__ __launch_bounds__(256, 2) void matfix(
    const float* __restrict__ Wv, const float* __restrict__ bv)
{
    extern __shared__ float smf[];
    const unsigned sb = smem_u32(smf);
    const int ch = blockIdx.x, kk = blockIdx.y, b = blockIdx.z;
    const int tid = threadIdx.x, lane = tid & 31, wid = tid >> 5;
    const int wm = wid & 3, wn = wid >> 2;

    float* xs   = smf + MAUX;
    float* ksm  = xs + 256;
    float* dsum = ksm + 128;
    xs[tid] = g_xsum[b*NC + tid];
    if (tid < 128) ksm[tid] = g_Ksum[b*NM + tid];
    __syncthreads();

    const float* WA = Wv + (size_t)ch*128*NC + kk*128;
    const float* KB = g_kxT + (size_t)b*NC*NM + (size_t)(kk*128)*NM;

    const int dn = tid & 127, dh = tid >> 7;
    float vsp = 0.f;
    float acc[2][8][4] = {};

    fillT36<256>(sb, WA, NC, tid);
    fillKN<256>(sb + 4608*4, KB, NM, tid);
    CPA_COMMIT();
    for (int it = 0; it < 4; ++it){
        const int cur = it & 1;
        if (it + 1 < 4){
            const int nx = (it+1) & 1, kt = (it+1)*32;
            fillT36<256>(sb + (nx*MSTG)*4,       WA + kt, NC, tid);
            fillKN<256>(sb + (nx*MSTG + 4608)*4, KB + (size_t)kt*NM, NM, tid);
            CPA_COMMIT(); CPA_WAIT1();
        } else CPA_WAIT0();
        __syncthreads();
        {
            const float* Ac = smf + cur*MSTG;
            const int kt = kk*128 + it*32;
            #pragma unroll
            for (int p = 0; p < 16; p++){
                int k = dh*16 + p;
                vsp = fmaf(Ac[dn*36 + k], xs[kt + k], vsp);
            }
        }
        mma_stage<36,1>(smf + cur*MSTG, smf + cur*MSTG + 4608, acc, wm, wn, lane);
        __syncthreads();
    }

    dsum[dh*128 + dn] = vsp;
    __syncthreads();
    if (tid < 128){
        float add = dsum[tid] + dsum[128 + tid];
        if (kk == 0) add += (float)NPIX * bv[ch*128 + tid];
        atomicAdd(&g_vsum[b*NC + ch*128 + tid], add);
    }

    const int lq = lane & 3, lr = lane >> 2;
    #pragma unroll
    for (int i = 0; i < 2; i++){
        int r = wm*32 + i*16 + lr;
        float bv0 = (kk == 0) ? bv[ch*128 + r]     : 0.f;
        float bv1 = (kk == 0) ? bv[ch*128 + r + 8] : 0.f;
        float* m0 = g_matT + ((size_t)b*NC + ch*128 + r)*NM;
        float* m1 = m0 + 8*NM;
        #pragma unroll
        for (int j = 0; j < 8; j++){
            int c = wn*64 + j*8 + 2*lq;
            atomicAdd(&m0[c],   acc[i][j][0] + bv0*ksm[c]);
            atomicAdd(&m0[c+1], acc[i][j][1] + bv0*ksm[c+1]);
            atomicAdd(&m1[c],   acc[i][j][2] + bv1*ksm[c]);
            atomicAdd(&m1[c+1], acc[i][j][3] + bv1*ksm[c+1]);
        }
    }
}

// ========== GEMM3: out[c][n]; single perfect wave (37 blocks/batch) ==========
// per batch: 256 units (ch, n-tile); block does ~7 units; matT reloaded on ch change.
#define GB   16896
#define GAUX (GB + 2*4352)       // ks128|svs128|stl128
#define OSMEM ((GAUX + 512)*4)
__global__ __launch_bounds__(128, 2) void gemm_out(
    const float* __restrict__ gamma, float* __restrict__ out)
{
    extern __shared__ float smf[];
    const unsigned sb = smem_u32(smf);
    const int bi = blockIdx.x, b = blockIdx.y;
    const int tid = threadIdx.x, lane = tid & 31, wid = tid >> 5;
    const int wm = wid & 1, wn = wid >> 1;
    const int u0 = (bi * 256) / NBLK, u1 = ((bi + 1) * 256) / NBLK;

    float* ks   = smf + GAUX;
    float* svs  = ks + 128;
    float* stl  = svs + 128;
    ks[tid] = g_Ksum[b*NM + tid] + EPSV;

    const int lq = lane & 3, lr = lane >> 2;
    int cur_ch = -1;

    for (int u = u0; u < u1; ++u){
        const int ch = u >> 7, nt = u & 127;
        if (ch != cur_ch){
            __syncthreads();   // prior tile done with old matT/svs
            fillA132<128>(sb, g_matT + ((size_t)b*NC + ch*128)*NM, NM, tid);
            CPA_COMMIT();      // pending matT group retires under first WAIT1 below
            svs[tid] = g_vsum[b*NC + ch*128 + tid];
            cur_ch = ch;
        }
        const int n0 = nt * 128;
        const float* Qb = g_QK + (size_t)b*256*NPIX + n0;

        float acc[4][8][4] = {};
        float ddv = 0.f;

        fillKN<128>(sb + GB*4, Qb, NPIX, tid);
        CPA_COMMIT();
        for (int it = 0; it < 4; ++it){
            const int cur = it & 1;
            if (it + 1 < 4){
                fillKN<128>(sb + (GB + ((it+1)&1)*4352)*4,
                            Qb + (size_t)(it+1)*32*NPIX, NPIX, tid);
                CPA_COMMIT(); CPA_WAIT1();
            } else CPA_WAIT0();
            __syncthreads();
            {
                const float* Bc = smf + GB + cur*4352;
                const int m0 = it*32;
                #pragma unroll
                for (int k = 0; k < 32; k++)
                    ddv = fmaf(Bc[k*136 + tid], ks[m0 + k], ddv);
            }
            mma_stage64<132,1>(smf + it*32, smf + GB + cur*4352, acc, wm, wn, lane);
            __syncthreads();
        }

        stl[tid] = gamma[0] / ((float)NPIX + ddv);
        __syncthreads();

        float* ob = out + ((size_t)b*NC + (size_t)cur_ch*128)*NPIX + n0;
        #pragma unroll
        for (int i = 0; i < 4; i++){
            int r = wm*64 + i*16 + lr;
            float v0 = svs[r], v1 = svs[r+8];
            #pragma unroll
            for (int j = 0; j < 8; j++){
                int c = wn*64 + j*8 + 2*lq;
                float t0 = stl[c], t1 = stl[c+1];
                *reinterpret_cast<float2*>(&ob[(size_t)r*NPIX + c]) =
                    make_float2(t0*(v0 + acc[i][j][0]), t1*(v0 + acc[i][j][1]));
                *reinterpret_cast<float2*>(&ob[(size_t)(r+8)*NPIX + c]) =
                    make_float2(t0*(v1 + acc[i][j][2]), t1*(v1 + acc[i][j][3]));
            }
        }
        __syncthreads();
    }
}

// ---------------- launch ----------------
extern "C" void kernel_launch(void* const* d_in, const int* in_sizes, int n_in,
                              void* d_out, int out_size)
{
    const float* x     = (const float*)d_in[0];
    const float* Wq    = (const float*)d_in[1];
    const float* bq    = (const float*)d_in[2];
    const float* Wk    = (const float*)d_in[3];
    const float* bk    = (const float*)d_in[4];
    const float* Wv    = (const float*)d_in[5];
    const float* bv    = (const float*)d_in[6];
    const float* gamma = (const float*)d_in[7];
    float* out = (float*)d_out;

    static bool attr_done = false;
    if (!attr_done){
        cudaFuncSetAttribute(gemm_qk,  cudaFuncAttributeMaxDynamicSharedMemorySize, QSMEM);
        cudaFuncSetAttribute(gemm_km,  cudaFuncAttributeMaxDynamicSharedMemorySize, KSMEM);
        cudaFuncSetAttribute(matfix,   cudaFuncAttributeMaxDynamicSharedMemorySize, MSMEM);
        cudaFuncSetAttribute(gemm_out, cudaFuncAttributeMaxDynamicSharedMemorySize, OSMEM);
        attr_done = true;
    }

    zero_small<<<1, 256>>>();
    gemm_qk<<<dim3(2, 128, NB), 128, QSMEM>>>(x, Wq, bq, Wk, bk);
    gemm_km<<<dim3(NBLK, NB), 128, KSMEM>>>(x);
    matfix<<<dim3(2, 2, NB), 256, MSMEM>>>(Wv, bv);
    gemm_out<<<dim3(NBLK, NB), 128, OSMEM>>>(gamma, out);
}